// round 1
// baseline (speedup 1.0000x reference)
#include <cuda_runtime.h>
#include <math.h>

#define NB 128
#define NH 256
#define NW 256
#define NC 64
#define TW 16
#define CSTR 257   // float2 stride per column tile to spread banks

// 128*256*256 complex floats = 64 MB static scratch (allocation-free)
__device__ float2 g_scratch[(size_t)NB * NH * NW];

// ---------------------------------------------------------------------------
// 256-point radix-2 DIT FFT in shared memory, 128 threads, input bit-reversed,
// output natural order. SIGN = -1 forward, +1 inverse (unscaled).
// ---------------------------------------------------------------------------
template <int SIGN>
__device__ __forceinline__ void fft256_shared(float2* s, int t) {
#pragma unroll
    for (int stage = 0; stage < 8; ++stage) {
        int half = 1 << stage;
        int pos = t & (half - 1);
        int idx1 = ((t >> stage) << (stage + 1)) | pos;
        int idx2 = idx1 + half;
        float wst = (float)SIGN * 6.283185307179586f / (float)(half * 2);
        float ang = wst * (float)pos;
        float sn, cs;
        __sincosf(ang, &sn, &cs);
        float2 a = s[idx1];
        float2 b = s[idx2];
        float tx = cs * b.x - sn * b.y;
        float ty = cs * b.y + sn * b.x;
        s[idx1] = make_float2(a.x + tx, a.y + ty);
        s[idx2] = make_float2(a.x - tx, a.y - ty);
        __syncthreads();
    }
}

// ---------------------------------------------------------------------------
// Same FFT but for TW=16 columns in one block of 256 threads.
// Thread t: column wl = t&15, butterfly worker jb = t>>4 handles j = jb+16*i.
// ---------------------------------------------------------------------------
template <int SIGN>
__device__ __forceinline__ void fft256_cols(float2* s, int t) {
    int wl = t & 15;
    int jb = t >> 4;
    float2* col = s + wl * CSTR;
#pragma unroll
    for (int stage = 0; stage < 8; ++stage) {
        int half = 1 << stage;
        float wst = (float)SIGN * 6.283185307179586f / (float)(half * 2);
#pragma unroll
        for (int i = 0; i < 8; ++i) {
            int j = jb + (i << 4);
            int pos = j & (half - 1);
            int idx1 = ((j >> stage) << (stage + 1)) | pos;
            int idx2 = idx1 + half;
            float ang = wst * (float)pos;
            float sn, cs;
            __sincosf(ang, &sn, &cs);
            float2 a = col[idx1];
            float2 b = col[idx2];
            float tx = cs * b.x - sn * b.y;
            float ty = cs * b.y + sn * b.x;
            col[idx1] = make_float2(a.x + tx, a.y + ty);
            col[idx2] = make_float2(a.x - tx, a.y - ty);
        }
        __syncthreads();
    }
}

// ---------------------------------------------------------------------------
// Pass 1: forward FFT along W for every (b,h) row. Real input.
// ---------------------------------------------------------------------------
__global__ void k_rowfft(const float* __restrict__ x) {
    __shared__ float2 s[NW];
    int row = blockIdx.x;  // b*256 + h
    int t = threadIdx.x;   // 128
    const float* xr = x + (size_t)row * NW;
#pragma unroll
    for (int i = t; i < NW; i += 128) {
        int r = __brev(i) >> 24;
        s[r] = make_float2(xr[i], 0.0f);
    }
    __syncthreads();
    fft256_shared<-1>(s, t);
    float2* o = g_scratch + (size_t)row * NW;
#pragma unroll
    for (int i = t; i < NW; i += 128) o[i] = s[i];
}

// ---------------------------------------------------------------------------
// Pass 2 (fused): forward FFT along H, mask multiply (with the fftshift /
// ifftshift index remap folded in), inverse FFT along H. One block handles
// one batch b and a tile of TW=16 adjacent columns. In-place on scratch.
// Mask: G[b,h,w] = F[b,h,w] * m[(b+64)%128, (h+128)%256, (w+128)%256]
// where m[b',h',w'] = (cid[h',w'] < 64) ? PI[b', cid] : 1.0
// The bit-reversal permutation needed before the inverse FFT is fused into
// the mask step as an involution pair swap.
// ---------------------------------------------------------------------------
__global__ void k_colfft_mask(const float* __restrict__ pi,
                              const int* __restrict__ cid) {
    __shared__ float2 s[TW * CSTR];
    __shared__ float sPI[NC];
    int t = threadIdx.x;       // 256
    int b = blockIdx.y;        // 0..127
    int w0 = blockIdx.x * TW;  // column tile base
    int bp = (b + 64) & 127;
    if (t < NC) sPI[t] = pi[bp * NC + t];

    float2* g = g_scratch + (size_t)b * NH * NW;

    // load columns, bit-reversing the h index
    for (int idx = t; idx < TW * NH; idx += 256) {
        int h = idx >> 4;
        int wl = idx & 15;
        float2 v = g[h * NW + w0 + wl];
        int r = __brev(h) >> 24;
        s[wl * CSTR + r] = v;
    }
    __syncthreads();

    fft256_cols<-1>(s, t);

    // mask multiply + bit-reverse permute (pair swap, h <-> rev(h))
    for (int idx = t; idx < TW * NH; idx += 256) {
        int h = idx >> 4;
        int wl = idx & 15;
        int r = __brev(h) >> 24;
        if (h > r) continue;
        int wp = (w0 + wl + 128) & 255;
        int hp = (h + 128) & 255;
        int c1 = cid[hp * NW + wp];
        float m1 = (c1 < NC) ? sPI[c1] : 1.0f;
        float2* col = s + wl * CSTR;
        if (h == r) {
            float2 v = col[h];
            col[h] = make_float2(v.x * m1, v.y * m1);
        } else {
            int rp = (r + 128) & 255;
            int c2 = cid[rp * NW + wp];
            float m2 = (c2 < NC) ? sPI[c2] : 1.0f;
            float2 vh = col[h];
            float2 vr = col[r];
            col[r] = make_float2(vh.x * m1, vh.y * m1);
            col[h] = make_float2(vr.x * m2, vr.y * m2);
        }
    }
    __syncthreads();

    fft256_cols<1>(s, t);

    // store back (natural order, coalesced)
    for (int idx = t; idx < TW * NH; idx += 256) {
        int h = idx >> 4;
        int wl = idx & 15;
        g[h * NW + w0 + wl] = s[wl * CSTR + h];
    }
}

// ---------------------------------------------------------------------------
// Pass 3: inverse FFT along W, magnitude, write all 3 output channels.
// Full 1/(256*256) scaling applied here.
// ---------------------------------------------------------------------------
__global__ void k_irow_out(const float* __restrict__ x,
                           float* __restrict__ out) {
    __shared__ float2 s[NW];
    int row = blockIdx.x;  // b*256 + h
    int t = threadIdx.x;   // 128
    int b = row >> 8;
    int h = row & 255;
    const float2* g = g_scratch + (size_t)row * NW;
#pragma unroll
    for (int i = t; i < NW; i += 128) {
        int r = __brev(i) >> 24;
        s[r] = g[i];
    }
    __syncthreads();
    fft256_shared<1>(s, t);

    const float* xr = x + (size_t)row * NW;
    size_t o0 = ((size_t)(b * 3 + 0) * NH + h) * NW;
    size_t o1 = ((size_t)(b * 3 + 1) * NH + h) * NW;
    size_t o2 = ((size_t)(b * 3 + 2) * NH + h) * NW;
    const float sc = 1.0f / 65536.0f;
#pragma unroll
    for (int i = t; i < NW; i += 128) {
        float2 v = s[i];
        float mag = sqrtf(v.x * v.x + v.y * v.y) * sc;
        float xv = xr[i];
        out[o0 + i] = xv;
        out[o1 + i] = mag;
        out[o2 + i] = fabsf(mag - xv);
    }
}

// ---------------------------------------------------------------------------
// Pass 4: pass-through copy of pattern_importance to the output tail.
// ---------------------------------------------------------------------------
__global__ void k_copy_pi(const float* __restrict__ pi,
                          float* __restrict__ out) {
    int i = blockIdx.x * blockDim.x + threadIdx.x;
    if (i < NB * NC) out[(size_t)NB * 3 * NH * NW + i] = pi[i];
}

extern "C" void kernel_launch(void* const* d_in, const int* in_sizes, int n_in,
                              void* d_out, int out_size) {
    const float* x = (const float*)d_in[0];    // [128,256,256] f32
    const float* pi = (const float*)d_in[1];   // [128,64]      f32
    const int* cid = (const int*)d_in[2];      // [256,256]     i32
    float* out = (float*)d_out;                // [128,3,256,256] + [128,64]

    k_rowfft<<<NB * NH, 128>>>(x);
    k_colfft_mask<<<dim3(NW / TW, NB), 256>>>(pi, cid);
    k_irow_out<<<NB * NH, 128>>>(x, out);
    k_copy_pi<<<(NB * NC + 255) / 256, 256>>>(pi, out);
}

// round 2
// speedup vs baseline: 3.6995x; 3.6995x over previous
#include <cuda_runtime.h>
#include <math.h>

#define NB 128
#define NH 256
#define NW 256
#define NC 64
#define CSTR 257   // float2 stride per lane-row in smem tile (conflict-free)

// 128*256*256 complex floats = 64 MB static scratch (allocation-free)
__device__ float2 g_scratch[(size_t)NB * NH * NW];

__device__ __forceinline__ float2 cadd(float2 a, float2 b){ return make_float2(a.x+b.x, a.y+b.y); }
__device__ __forceinline__ float2 csub(float2 a, float2 b){ return make_float2(a.x-b.x, a.y-b.y); }
__device__ __forceinline__ float2 cmul(float2 a, float2 b){
    return make_float2(fmaf(a.x, b.x, -a.y*b.y), fmaf(a.x, b.y, a.y*b.x));
}
// multiply by -i (forward, SIGN=-1) or +i (inverse, SIGN=+1)
template<int SIGN>
__device__ __forceinline__ float2 rot90(float2 a){
    return (SIGN < 0) ? make_float2(a.y, -a.x) : make_float2(-a.y, a.x);
}
// table holds exp(-2*pi*i*j/256); conjugate for inverse
template<int SIGN>
__device__ __forceinline__ float2 twget(const float2* tw, int j){
    float2 w = tw[j];
    return (SIGN < 0) ? w : make_float2(w.x, -w.y);
}

// Fully-unrolled 16-point DFT in registers (DIF radix-4 x2), natural in/out order.
// r_out[k] = sum_n r_in[n] * exp(SIGN*2*pi*i*k*n/16)
template<int SIGN>
__device__ __forceinline__ void fft16(float2* r, const float2* tw){
    float2 v[16];
#pragma unroll
    for (int p = 0; p < 4; ++p){
        float2 a=r[p], b=r[p+4], c=r[p+8], d=r[p+12];
        float2 t0=cadd(a,c), t1=csub(a,c), t2=cadd(b,d);
        float2 t3=rot90<SIGN>(csub(b,d));
        float2 u0=cadd(t0,t2), u1=cadd(t1,t3), u2=csub(t0,t2), u3=csub(t1,t3);
        if (p){
            u1 = cmul(u1, twget<SIGN>(tw, 16*p));
            u2 = cmul(u2, twget<SIGN>(tw, 32*p));
            u3 = cmul(u3, twget<SIGN>(tw, 48*p));
        }
        v[p]=u0; v[4+p]=u1; v[8+p]=u2; v[12+p]=u3;
    }
#pragma unroll
    for (int m = 0; m < 4; ++m){
        float2 a=v[4*m], b=v[4*m+1], c=v[4*m+2], d=v[4*m+3];
        float2 t0=cadd(a,c), t1=csub(a,c), t2=cadd(b,d);
        float2 t3=rot90<SIGN>(csub(b,d));
        r[m]    = cadd(t0,t2);
        r[4+m]  = cadd(t1,t3);
        r[8+m]  = csub(t0,t2);
        r[12+m] = csub(t1,t3);
    }
}

#define BUILD_TW() do { \
    float sn_, cs_; sincospif(-(float)t * (1.0f/128.0f), &sn_, &cs_); \
    stw[t] = make_float2(cs_, sn_); } while(0)

// ---------------------------------------------------------------------------
// Pass 1: forward FFT along W. 16 rows per block, 256 threads.
// 256-pt FFT = fft16 over n2 (regs) -> twiddle -> smem transpose -> fft16 over n1.
// ---------------------------------------------------------------------------
__global__ void __launch_bounds__(256) k_rowfft(const float* __restrict__ x){
    __shared__ float2 s[16*CSTR];
    __shared__ float2 stw[256];
    int t = threadIdx.x;
    BUILD_TW();
    int row0 = blockIdx.x * 16;
    const float* xp = x + (size_t)row0 * NW;
#pragma unroll
    for (int k = 0; k < 16; ++k){
        int idx = t + k*256;
        int rl = idx >> 8, i = idx & 255;
        s[rl*CSTR + i] = make_float2(xp[idx], 0.0f);
    }
    __syncthreads();
    int wl = t & 15, hi = t >> 4;       // hi = n1 for step 1
    float2 r[16];
    float2* srow = s + wl*CSTR;
#pragma unroll
    for (int n2 = 0; n2 < 16; ++n2) r[n2] = srow[16*n2 + hi];
    fft16<-1>(r, stw);                  // over n2 -> regs indexed by k2
#pragma unroll
    for (int k2 = 1; k2 < 16; ++k2) r[k2] = cmul(r[k2], twget<-1>(stw, k2*hi));
    __syncthreads();
#pragma unroll
    for (int k2 = 0; k2 < 16; ++k2) srow[k2*16 + hi] = r[k2];
    __syncthreads();
#pragma unroll
    for (int i = 0; i < 16; ++i) r[i] = srow[hi*16 + i];   // thread: k2 = hi, regs over n1
    fft16<-1>(r, stw);                  // over n1 -> regs indexed by k1: X[16*k1 + k2]
    __syncthreads();
#pragma unroll
    for (int k1 = 0; k1 < 16; ++k1) srow[16*k1 + hi] = r[k1];
    __syncthreads();
    float2* gp = g_scratch + (size_t)row0 * NW;
#pragma unroll
    for (int k = 0; k < 16; ++k){
        int idx = t + k*256;
        int rl = idx >> 8, i = idx & 255;
        gp[idx] = s[rl*CSTR + i];
    }
}

// ---------------------------------------------------------------------------
// Pass 2: forward FFT along H + mask (fftshift folded into index remap) +
// inverse FFT along H, fused. One block = (batch b, 16-column tile).
// ---------------------------------------------------------------------------
__global__ void __launch_bounds__(256) k_colfft_mask(const float* __restrict__ pi,
                                                     const int* __restrict__ cid){
    __shared__ float2 s[16*CSTR];
    __shared__ float2 stw[256];
    __shared__ float sPI[NC];
    int t = threadIdx.x;
    BUILD_TW();
    int b  = blockIdx.y;
    int w0 = blockIdx.x * 16;
    if (t < NC) sPI[t] = pi[((b + 64) & 127) * NC + t];
    float2* g = g_scratch + (size_t)b * NH * NW;
#pragma unroll
    for (int k = 0; k < 16; ++k){
        int idx = t + k*256;
        int h = idx >> 4, w = idx & 15;
        s[w*CSTR + h] = g[h*NW + w0 + w];
    }
    __syncthreads();
    int wl = t & 15, hi = t >> 4;
    int wp = (w0 + wl + 128) & 255;
    float2 r[16];
    float2* scol = s + wl*CSTR;
    // forward over h
#pragma unroll
    for (int n2 = 0; n2 < 16; ++n2) r[n2] = scol[16*n2 + hi];
    fft16<-1>(r, stw);
#pragma unroll
    for (int k2 = 1; k2 < 16; ++k2) r[k2] = cmul(r[k2], twget<-1>(stw, k2*hi));
    __syncthreads();
#pragma unroll
    for (int k2 = 0; k2 < 16; ++k2) scol[k2*16 + hi] = r[k2];
    __syncthreads();
#pragma unroll
    for (int i = 0; i < 16; ++i) r[i] = scol[hi*16 + i];   // thread: k2 = hi
    fft16<-1>(r, stw);                                     // regs over k1: X[16*k1 + hi]
    // mask multiply in registers: h = 16*k1 + hi
#pragma unroll
    for (int k1 = 0; k1 < 16; ++k1){
        int hp = (16*k1 + hi + 128) & 255;
        int c = __ldg(&cid[hp*NW + wp]);
        float m = (c < NC) ? sPI[c] : 1.0f;
        r[k1].x *= m; r[k1].y *= m;
    }
    // inverse over h (unscaled)
    fft16<1>(r, stw);                                      // over k1 -> regs over n1
#pragma unroll
    for (int n1 = 1; n1 < 16; ++n1) r[n1] = cmul(r[n1], twget<1>(stw, n1*hi));
    __syncthreads();
#pragma unroll
    for (int n1 = 0; n1 < 16; ++n1) scol[n1*16 + hi] = r[n1];
    __syncthreads();
#pragma unroll
    for (int i = 0; i < 16; ++i) r[i] = scol[hi*16 + i];   // thread: n1 = hi, regs over k2
    fft16<1>(r, stw);                                      // over k2 -> regs over n2
    __syncthreads();
#pragma unroll
    for (int n2 = 0; n2 < 16; ++n2) scol[16*n2 + hi] = r[n2];
    __syncthreads();
#pragma unroll
    for (int k = 0; k < 16; ++k){
        int idx = t + k*256;
        int h = idx >> 4, w = idx & 15;
        g[h*NW + w0 + w] = s[w*CSTR + h];
    }
}

// ---------------------------------------------------------------------------
// Pass 3: inverse FFT along W + magnitude + write all 3 output channels.
// 1/(256*256) scaling applied here.
// ---------------------------------------------------------------------------
__global__ void __launch_bounds__(256) k_irow_out(const float* __restrict__ x,
                                                  float* __restrict__ out){
    __shared__ float2 s[16*CSTR];
    __shared__ float2 stw[256];
    int t = threadIdx.x;
    BUILD_TW();
    int row0 = blockIdx.x * 16;
    const float2* gp = g_scratch + (size_t)row0 * NW;
#pragma unroll
    for (int k = 0; k < 16; ++k){
        int idx = t + k*256;
        int rl = idx >> 8, i = idx & 255;
        s[rl*CSTR + i] = gp[idx];
    }
    __syncthreads();
    int wl = t & 15, hi = t >> 4;       // hi = k2 for step 1
    float2 r[16];
    float2* srow = s + wl*CSTR;
#pragma unroll
    for (int k1 = 0; k1 < 16; ++k1) r[k1] = srow[16*k1 + hi];
    fft16<1>(r, stw);                   // over k1 -> regs over n1
#pragma unroll
    for (int n1 = 1; n1 < 16; ++n1) r[n1] = cmul(r[n1], twget<1>(stw, n1*hi));
    __syncthreads();
#pragma unroll
    for (int n1 = 0; n1 < 16; ++n1) srow[n1*16 + hi] = r[n1];
    __syncthreads();
#pragma unroll
    for (int i = 0; i < 16; ++i) r[i] = srow[hi*16 + i];   // thread: n1 = hi, regs over k2
    fft16<1>(r, stw);                   // over k2 -> regs over n2: y[16*n2 + n1]
    __syncthreads();
#pragma unroll
    for (int n2 = 0; n2 < 16; ++n2) srow[16*n2 + hi] = r[n2];
    __syncthreads();
    const float sc = 1.0f / 65536.0f;
    const float* xp = x + (size_t)row0 * NW;
#pragma unroll
    for (int k = 0; k < 16; ++k){
        int idx = t + k*256;
        int rl = idx >> 8, i = idx & 255;
        int row = row0 + rl;
        int bb = row >> 8, h = row & 255;
        float2 v = s[rl*CSTR + i];
        float mag = sqrtf(fmaf(v.x, v.x, v.y*v.y)) * sc;
        float xv = xp[idx];
        size_t base = ((size_t)(bb*3) * NH + h) * NW + i;
        out[base]                    = xv;
        out[base + (size_t)NH*NW]    = mag;
        out[base + 2*(size_t)NH*NW]  = fabsf(mag - xv);
    }
}

__global__ void k_copy_pi(const float* __restrict__ pi, float* __restrict__ out){
    int i = blockIdx.x * blockDim.x + threadIdx.x;
    if (i < NB * NC) out[(size_t)NB * 3 * NH * NW + i] = pi[i];
}

extern "C" void kernel_launch(void* const* d_in, const int* in_sizes, int n_in,
                              void* d_out, int out_size) {
    const float* x  = (const float*)d_in[0];   // [128,256,256] f32
    const float* pi = (const float*)d_in[1];   // [128,64]      f32
    const int* cid  = (const int*)d_in[2];     // [256,256]     i32
    float* out = (float*)d_out;                // [128,3,256,256] + [128,64]

    k_rowfft<<<(NB*NH)/16, 256>>>(x);
    k_colfft_mask<<<dim3(NW/16, NB), 256>>>(pi, cid);
    k_irow_out<<<(NB*NH)/16, 256>>>(x, out);
    k_copy_pi<<<(NB*NC + 255)/256, 256>>>(pi, out);
}